// round 1
// baseline (speedup 1.0000x reference)
#include <cuda_runtime.h>
#include <cstdint>
#include <cfloat>

// Problem constants
#define BATCH   2
#define SEQ     2048
#define DMODEL  1024
#define NHEADS  16
#define HDIM    64
#define QKV_LD  3072
#define NTOK    (BATCH * SEQ)      // 4096
#define WINDOW  128
#define STRIDE  64

// Scratch (device globals: no allocation allowed)
__device__ float g_qkv[(size_t)NTOK * QKV_LD];   // 4096 x 3072
__device__ float g_y[(size_t)NTOK * DMODEL];     // 4096 x 1024

// ---------------------------------------------------------------------------
// SGEMM: C[M,N] = A[M,K] @ B[K,N], row-major, 128x128 block tile, BK=8,
// 256 threads, 8x8 register microtile. M,N multiples of 128; K multiple of 8.
// ---------------------------------------------------------------------------
__global__ __launch_bounds__(256) void sgemm128(
    const float* __restrict__ A, const float* __restrict__ B,
    float* __restrict__ C, int M, int N, int K)
{
    __shared__ float As[8][132];   // [k][m], padded to kill store conflicts
    __shared__ float Bs[8][128];   // [k][n]

    const int tid = threadIdx.x;
    const int tx = tid & 15;        // 0..15 -> N direction
    const int ty = tid >> 4;        // 0..15 -> M direction
    const int row0 = blockIdx.y * 128;
    const int col0 = blockIdx.x * 128;

    // A tile loader: 128 rows x 8 cols, one float4 per thread
    const int arow = tid >> 1;
    const int acol = (tid & 1) * 4;
    // B tile loader: 8 rows x 128 cols, one float4 per thread
    const int brow = tid >> 5;
    const int bcol = (tid & 31) * 4;

    const float* Aptr = A + (size_t)(row0 + arow) * K + acol;
    const float* Bptr = B + (size_t)brow * N + col0 + bcol;

    float acc[8][8];
#pragma unroll
    for (int i = 0; i < 8; ++i)
#pragma unroll
        for (int j = 0; j < 8; ++j) acc[i][j] = 0.0f;

    for (int k0 = 0; k0 < K; k0 += 8) {
        float4 a = *(const float4*)(Aptr + k0);
        As[acol + 0][arow] = a.x;
        As[acol + 1][arow] = a.y;
        As[acol + 2][arow] = a.z;
        As[acol + 3][arow] = a.w;
        float4 b = *(const float4*)(Bptr + (size_t)k0 * N);
        *(float4*)&Bs[brow][bcol] = b;
        __syncthreads();

#pragma unroll
        for (int k = 0; k < 8; ++k) {
            float4 a0 = *(const float4*)&As[k][ty * 8];
            float4 a1 = *(const float4*)&As[k][ty * 8 + 4];
            float4 b0 = *(const float4*)&Bs[k][tx * 8];
            float4 b1 = *(const float4*)&Bs[k][tx * 8 + 4];
            float ar[8] = {a0.x, a0.y, a0.z, a0.w, a1.x, a1.y, a1.z, a1.w};
            float br[8] = {b0.x, b0.y, b0.z, b0.w, b1.x, b1.y, b1.z, b1.w};
#pragma unroll
            for (int i = 0; i < 8; ++i)
#pragma unroll
                for (int j = 0; j < 8; ++j)
                    acc[i][j] = fmaf(ar[i], br[j], acc[i][j]);
        }
        __syncthreads();
    }

    float* Cptr = C + (size_t)(row0 + ty * 8) * N + col0 + tx * 8;
#pragma unroll
    for (int i = 0; i < 8; ++i) {
        *(float4*)(Cptr + (size_t)i * N)     = make_float4(acc[i][0], acc[i][1], acc[i][2], acc[i][3]);
        *(float4*)(Cptr + (size_t)i * N + 4) = make_float4(acc[i][4], acc[i][5], acc[i][6], acc[i][7]);
    }
}

// ---------------------------------------------------------------------------
// Sparse flash attention.
// Grid: (S/64, NHEADS, BATCH). Block: 256 threads (16x16 logical).
// For query block t (rows r0..r0+63):
//   - window tiles: kb in [max(0,t-2), t] (mask handles window+causal+global)
//   - one gathered "global tile": columns {g*64 : 0 <= g <= t-3} (<= 30 valid)
// Online softmax, P staged via smem for the PV product.
// Shared (dynamic): Qt[64][68] Kt[64][68] Vs[64][68] Ps[64][68] = 69632 B.
// ---------------------------------------------------------------------------
#define APITCH 68
#define ATTN_SMEM (4 * 64 * APITCH * (int)sizeof(float))

__global__ __launch_bounds__(256) void sparse_attn(
    const float* __restrict__ qkv, float* __restrict__ y)
{
    extern __shared__ float sm[];
    float* Qt = sm;                     // [d][i]  transposed
    float* Kt = Qt + 64 * APITCH;       // [d][j]  transposed
    float* Vs = Kt + 64 * APITCH;       // [j][d]
    float* Ps = Vs + 64 * APITCH;       // [i][j]

    const int t   = blockIdx.x;         // query block index
    const int h   = blockIdx.y;
    const int b   = blockIdx.z;
    const int tid = threadIdx.x;
    const int tx  = tid & 15;           // key/col dir (4 cols each)
    const int ty  = tid >> 4;           // query/row dir (4 rows each)
    const int r0  = t * 64;

    const size_t base = (size_t)b * SEQ * QKV_LD;

    // Load Q tile transposed: Qt[d][i] = q[r0+i][d]
    for (int e = tid; e < 1024; e += 256) {
        const int tok = e >> 4;
        const int d4  = (e & 15) * 4;
        float4 v = *(const float4*)(qkv + base + (size_t)(r0 + tok) * QKV_LD + h * HDIM + d4);
        Qt[(d4 + 0) * APITCH + tok] = v.x;
        Qt[(d4 + 1) * APITCH + tok] = v.y;
        Qt[(d4 + 2) * APITCH + tok] = v.z;
        Qt[(d4 + 3) * APITCH + tok] = v.w;
    }

    float m_i[4], l_i[4], acc[4][4];
#pragma unroll
    for (int i = 0; i < 4; ++i) {
        m_i[i] = -3.0e38f;
        l_i[i] = 0.0f;
#pragma unroll
        for (int j = 0; j < 4; ++j) acc[i][j] = 0.0f;
    }

    const int kb_start = (t >= 2) ? (t - 2) : 0;
    const int n_win    = t - kb_start + 1;
    const int nglob    = (t >= 3) ? (t - 2) : 0;
    const int n_tiles  = n_win + (nglob > 0 ? 1 : 0);

    for (int it = 0; it < n_tiles; ++it) {
        const bool is_glob = (it == n_win);
        const int  kcol0   = (kb_start + it) * 64;   // valid only for window tiles

        __syncthreads();   // previous Ps/Vs consumers done before overwrite

        // Load K (transposed) and V tiles
        for (int e = tid; e < 1024; e += 256) {
            const int tok = e >> 4;
            const int d4  = (e & 15) * 4;
            int key;
            bool valid;
            if (is_glob) { key = tok * STRIDE; valid = (tok < nglob); }
            else         { key = kcol0 + tok;  valid = true; }
            float4 kv, vv;
            if (valid) {
                const float* kp = qkv + base + (size_t)key * QKV_LD + DMODEL + h * HDIM + d4;
                kv = *(const float4*)kp;
                vv = *(const float4*)(kp + DMODEL);
            } else {
                kv = make_float4(0.f, 0.f, 0.f, 0.f);
                vv = kv;
            }
            Kt[(d4 + 0) * APITCH + tok] = kv.x;
            Kt[(d4 + 1) * APITCH + tok] = kv.y;
            Kt[(d4 + 2) * APITCH + tok] = kv.z;
            Kt[(d4 + 3) * APITCH + tok] = kv.w;
            *(float4*)&Vs[tok * APITCH + d4] = vv;
        }
        __syncthreads();

        // S = scale * Q K^T (4x4 per thread)
        float s[4][4];
#pragma unroll
        for (int i = 0; i < 4; ++i)
#pragma unroll
            for (int j = 0; j < 4; ++j) s[i][j] = 0.0f;

#pragma unroll 8
        for (int k = 0; k < 64; ++k) {
            float4 q4 = *(const float4*)&Qt[k * APITCH + ty * 4];
            float4 k4 = *(const float4*)&Kt[k * APITCH + tx * 4];
            float qa[4] = {q4.x, q4.y, q4.z, q4.w};
            float ka[4] = {k4.x, k4.y, k4.z, k4.w};
#pragma unroll
            for (int i = 0; i < 4; ++i)
#pragma unroll
                for (int j = 0; j < 4; ++j)
                    s[i][j] = fmaf(qa[i], ka[j], s[i][j]);
        }

        // mask + scale
#pragma unroll
        for (int i = 0; i < 4; ++i) {
            const int row = r0 + ty * 4 + i;
#pragma unroll
            for (int j = 0; j < 4; ++j) {
                bool ok;
                if (is_glob) {
                    ok = (tx * 4 + j) < nglob;    // gathered cols always attended
                } else {
                    const int col = kcol0 + tx * 4 + j;
                    ok = (col <= row) && ((row - col) <= (WINDOW - 1) || (col & (STRIDE - 1)) == 0);
                }
                s[i][j] = ok ? s[i][j] * 0.125f : -3.0e38f;
            }
        }

        // online softmax (row groups of 16 lanes: same ty = contiguous half-warp)
#pragma unroll
        for (int i = 0; i < 4; ++i) {
            float mx = fmaxf(fmaxf(s[i][0], s[i][1]), fmaxf(s[i][2], s[i][3]));
#pragma unroll
            for (int off = 8; off >= 1; off >>= 1)
                mx = fmaxf(mx, __shfl_xor_sync(0xffffffffu, mx, off, 16));
            const float mnew = fmaxf(m_i[i], mx);
            const float alpha = __expf(m_i[i] - mnew);
            float rs = 0.0f;
#pragma unroll
            for (int j = 0; j < 4; ++j) {
                const float p = __expf(s[i][j] - mnew);
                Ps[(ty * 4 + i) * APITCH + tx * 4 + j] = p;
                rs += p;
            }
#pragma unroll
            for (int off = 8; off >= 1; off >>= 1)
                rs += __shfl_xor_sync(0xffffffffu, rs, off, 16);
            l_i[i] = l_i[i] * alpha + rs;
            m_i[i] = mnew;
#pragma unroll
            for (int j = 0; j < 4; ++j) acc[i][j] *= alpha;
        }
        __syncthreads();

        // O += P @ V
#pragma unroll 8
        for (int j = 0; j < 64; ++j) {
            float4 v4 = *(const float4*)&Vs[j * APITCH + tx * 4];
            float va[4] = {v4.x, v4.y, v4.z, v4.w};
            float pa[4];
#pragma unroll
            for (int i = 0; i < 4; ++i) pa[i] = Ps[(ty * 4 + i) * APITCH + j];
#pragma unroll
            for (int i = 0; i < 4; ++i)
#pragma unroll
                for (int d = 0; d < 4; ++d)
                    acc[i][d] = fmaf(pa[i], va[d], acc[i][d]);
        }
    }

    // normalize + write y[b, row, h*64 + d]
#pragma unroll
    for (int i = 0; i < 4; ++i) {
        const float inv = 1.0f / l_i[i];
        const size_t row = (size_t)b * SEQ + r0 + ty * 4 + i;
        float4 o = make_float4(acc[i][0] * inv, acc[i][1] * inv,
                               acc[i][2] * inv, acc[i][3] * inv);
        *(float4*)&y[row * DMODEL + h * HDIM + tx * 4] = o;
    }
}

// ---------------------------------------------------------------------------
extern "C" void kernel_launch(void* const* d_in, const int* in_sizes, int n_in,
                              void* d_out, int out_size)
{
    const float* x     = (const float*)d_in[0];
    const float* Wqkv  = (const float*)d_in[1];
    const float* Wproj = (const float*)d_in[2];
    float* out = (float*)d_out;

    float *qkv = nullptr, *y = nullptr;
    cudaGetSymbolAddress((void**)&qkv, g_qkv);
    cudaGetSymbolAddress((void**)&y, g_y);

    // 1) QKV projection: [4096,1024] @ [1024,3072]
    sgemm128<<<dim3(QKV_LD / 128, NTOK / 128), 256>>>(x, Wqkv, qkv, NTOK, QKV_LD, DMODEL);

    // 2) Sparse attention
    cudaFuncSetAttribute(sparse_attn, cudaFuncAttributeMaxDynamicSharedMemorySize, ATTN_SMEM);
    sparse_attn<<<dim3(SEQ / 64, NHEADS, BATCH), 256, ATTN_SMEM>>>(qkv, y);

    // 3) Output projection: [4096,1024] @ [1024,1024]
    sgemm128<<<dim3(DMODEL / 128, NTOK / 128), 256>>>(y, Wproj, out, NTOK, DMODEL, DMODEL);
}

// round 3
// speedup vs baseline: 2.0179x; 2.0179x over previous
#include <cuda_runtime.h>
#include <cstdint>
#include <cfloat>

// Problem constants
#define BATCH   2
#define SEQ     2048
#define DMODEL  1024
#define NHEADS  16
#define HDIM    64
#define QKV_LD  3072
#define NTOK    (BATCH * SEQ)      // 4096
#define WINDOW  128
#define STRIDE  64

// Scratch (device globals: no allocation allowed)
__device__ float g_qkv[(size_t)NTOK * QKV_LD];   // 4096 x 3072
__device__ float g_y[(size_t)NTOK * DMODEL];     // 4096 x 1024

// ---------------------------------------------------------------------------
// TF32 tensor-core GEMM: C[M,N] = A[M,K] @ B[K,N], row-major.
// 128x128 CTA tile, BK=32, 256 threads = 8 warps in 2(M) x 4(N) grid,
// warp tile 64x32 -> 4x4 grid of m16n8k8 tf32 mma.sync.
// A fragments via ldmatrix.x4.b16 (tf32 = b16 pair trick); B via scalar LDS
// from a pitch-136 [k][n] tile (pitch ≡ 8 mod 32 -> banks 8k+n distinct).
// Smem double-buffered (dynamic, 70KB); gmem prefetched through registers.
// Requires M%128==0, N%128==0, K%32==0.
// ---------------------------------------------------------------------------
#define AP 36    // As row pitch (floats)
#define BP 136   // Bs row pitch (floats), rows are 128 wide + 8 pad
#define GEMM_SMEM ((2 * 128 * AP + 2 * 32 * BP) * (int)sizeof(float))  // 71680 B

__device__ __forceinline__ unsigned f2tf(float f) {
    unsigned u;
    asm("cvt.rna.tf32.f32 %0, %1;" : "=r"(u) : "f"(f));
    return u;
}

__global__ __launch_bounds__(256) void tgemm(
    const float* __restrict__ A, const float* __restrict__ B,
    float* __restrict__ C, int M, int N, int K)
{
    extern __shared__ float dynsm[];
    float* Asm0 = dynsm;                         // [2][128*AP], [m][k]
    float* Bsm0 = dynsm + 2 * 128 * AP;          // [2][32*BP],  [k][n]

    const int tid  = threadIdx.x;
    const int lane = tid & 31;
    const int wid  = tid >> 5;
    const int warp_m = wid & 1;          // 0..1
    const int warp_n = wid >> 1;         // 0..3

    const int row0 = blockIdx.y * 128;
    const int col0 = blockIdx.x * 128;

    // gmem tile loaders (each thread: 16 consecutive floats = 4 float4)
    const int arow = tid >> 1;            // 0..127
    const int acol = (tid & 1) * 16;      // 0 or 16
    const int brow = tid >> 3;            // 0..31
    const int bcol = (tid & 7) * 16;      // 0..112

    const float* Ag = A + (size_t)(row0 + arow) * K + acol;
    const float* Bg = B + (size_t)brow * N + col0 + bcol;

    float acc[4][4][4];
#pragma unroll
    for (int mi = 0; mi < 4; ++mi)
#pragma unroll
        for (int ni = 0; ni < 4; ++ni)
#pragma unroll
            for (int e = 0; e < 4; ++e) acc[mi][ni][e] = 0.0f;

    const int nk = K / 32;

    // ---- prologue: stage tile 0 ----
    float4 ra[4], rb[4];
#pragma unroll
    for (int j = 0; j < 4; ++j) ra[j] = *(const float4*)(Ag + 4 * j);
#pragma unroll
    for (int j = 0; j < 4; ++j) rb[j] = *(const float4*)(Bg + 4 * j);
#pragma unroll
    for (int j = 0; j < 4; ++j) {
        float4 t;
        t.x = __uint_as_float(f2tf(ra[j].x));
        t.y = __uint_as_float(f2tf(ra[j].y));
        t.z = __uint_as_float(f2tf(ra[j].z));
        t.w = __uint_as_float(f2tf(ra[j].w));
        *(float4*)&Asm0[arow * AP + acol + 4 * j] = t;
        float4 u;
        u.x = __uint_as_float(f2tf(rb[j].x));
        u.y = __uint_as_float(f2tf(rb[j].y));
        u.z = __uint_as_float(f2tf(rb[j].z));
        u.w = __uint_as_float(f2tf(rb[j].w));
        *(float4*)&Bsm0[brow * BP + bcol + 4 * j] = u;
    }
    __syncthreads();

    // per-lane ldmatrix addressing
    const int lrow  = lane & 15;                 // row within 16-row tile
    const int lksel = (lane & 16) ? 4 : 0;       // col half selector (tf32 units)

    for (int it = 0; it < nk; ++it) {
        const int cur = it & 1;

        // prefetch next tile (gmem -> regs)
        if (it + 1 < nk) {
            const float* ap = Ag + (it + 1) * 32;
#pragma unroll
            for (int j = 0; j < 4; ++j) ra[j] = *(const float4*)(ap + 4 * j);
            const float* bp = B + (size_t)((it + 1) * 32 + brow) * N + col0 + bcol;
#pragma unroll
            for (int j = 0; j < 4; ++j) rb[j] = *(const float4*)(bp + 4 * j);
        }

        // ---- compute from smem[cur] ----
        float* Ac = Asm0 + cur * 128 * AP;
        float* Bc = Bsm0 + cur * 32 * BP;
        const unsigned smA = (unsigned)__cvta_generic_to_shared(Ac);
#pragma unroll
        for (int ks = 0; ks < 4; ++ks) {
            unsigned a[4][4];
#pragma unroll
            for (int mi = 0; mi < 4; ++mi) {
                unsigned ad = smA +
                    (((warp_m * 64 + mi * 16 + lrow) * AP + ks * 8 + lksel) << 2);
                asm volatile(
                    "ldmatrix.sync.aligned.m8n8.x4.shared.b16 {%0,%1,%2,%3}, [%4];"
                    : "=r"(a[mi][0]), "=r"(a[mi][1]), "=r"(a[mi][2]), "=r"(a[mi][3])
                    : "r"(ad));
            }
            unsigned b0[4], b1[4];
            const int krow = ks * 8 + (lane & 3);
            const int ncol = warp_n * 32 + (lane >> 2);
#pragma unroll
            for (int ni = 0; ni < 4; ++ni) {
                b0[ni] = __float_as_uint(Bc[krow * BP + ncol + ni * 8]);
                b1[ni] = __float_as_uint(Bc[(krow + 4) * BP + ncol + ni * 8]);
            }
#pragma unroll
            for (int mi = 0; mi < 4; ++mi)
#pragma unroll
                for (int ni = 0; ni < 4; ++ni) {
                    asm volatile(
                        "mma.sync.aligned.m16n8k8.row.col.f32.tf32.tf32.f32 "
                        "{%0,%1,%2,%3}, {%4,%5,%6,%7}, {%8,%9}, {%0,%1,%2,%3};"
                        : "+f"(acc[mi][ni][0]), "+f"(acc[mi][ni][1]),
                          "+f"(acc[mi][ni][2]), "+f"(acc[mi][ni][3])
                        : "r"(a[mi][0]), "r"(a[mi][1]), "r"(a[mi][2]), "r"(a[mi][3]),
                          "r"(b0[ni]), "r"(b1[ni]));
                }
        }

        // stage next tile (regs -> smem[cur^1])
        if (it + 1 < nk) {
            float* An = Asm0 + (cur ^ 1) * 128 * AP;
            float* Bn = Bsm0 + (cur ^ 1) * 32 * BP;
#pragma unroll
            for (int j = 0; j < 4; ++j) {
                float4 t;
                t.x = __uint_as_float(f2tf(ra[j].x));
                t.y = __uint_as_float(f2tf(ra[j].y));
                t.z = __uint_as_float(f2tf(ra[j].z));
                t.w = __uint_as_float(f2tf(ra[j].w));
                *(float4*)&An[arow * AP + acol + 4 * j] = t;
                float4 u;
                u.x = __uint_as_float(f2tf(rb[j].x));
                u.y = __uint_as_float(f2tf(rb[j].y));
                u.z = __uint_as_float(f2tf(rb[j].z));
                u.w = __uint_as_float(f2tf(rb[j].w));
                *(float4*)&Bn[brow * BP + bcol + 4 * j] = u;
            }
        }
        __syncthreads();
    }

    // ---- epilogue ----
    const int g  = lane >> 2;
    const int tg = lane & 3;
#pragma unroll
    for (int mi = 0; mi < 4; ++mi) {
#pragma unroll
        for (int ni = 0; ni < 4; ++ni) {
            const int row = row0 + warp_m * 64 + mi * 16 + g;
            const int col = col0 + warp_n * 32 + ni * 8 + 2 * tg;
            *(float2*)&C[(size_t)row * N + col] =
                make_float2(acc[mi][ni][0], acc[mi][ni][1]);
            *(float2*)&C[(size_t)(row + 8) * N + col] =
                make_float2(acc[mi][ni][2], acc[mi][ni][3]);
        }
    }
}

// ---------------------------------------------------------------------------
// Sparse flash attention (unchanged from R1).
// ---------------------------------------------------------------------------
#define APITCH 68
#define ATTN_SMEM (4 * 64 * APITCH * (int)sizeof(float))

__global__ __launch_bounds__(256) void sparse_attn(
    const float* __restrict__ qkv, float* __restrict__ y)
{
    extern __shared__ float sm[];
    float* Qt = sm;                     // [d][i]  transposed
    float* Kt = Qt + 64 * APITCH;       // [d][j]  transposed
    float* Vs = Kt + 64 * APITCH;       // [j][d]
    float* Ps = Vs + 64 * APITCH;       // [i][j]

    const int t   = blockIdx.x;
    const int h   = blockIdx.y;
    const int b   = blockIdx.z;
    const int tid = threadIdx.x;
    const int tx  = tid & 15;
    const int ty  = tid >> 4;
    const int r0  = t * 64;

    const size_t base = (size_t)b * SEQ * QKV_LD;

    for (int e = tid; e < 1024; e += 256) {
        const int tok = e >> 4;
        const int d4  = (e & 15) * 4;
        float4 v = *(const float4*)(qkv + base + (size_t)(r0 + tok) * QKV_LD + h * HDIM + d4);
        Qt[(d4 + 0) * APITCH + tok] = v.x;
        Qt[(d4 + 1) * APITCH + tok] = v.y;
        Qt[(d4 + 2) * APITCH + tok] = v.z;
        Qt[(d4 + 3) * APITCH + tok] = v.w;
    }

    float m_i[4], l_i[4], acc[4][4];
#pragma unroll
    for (int i = 0; i < 4; ++i) {
        m_i[i] = -3.0e38f;
        l_i[i] = 0.0f;
#pragma unroll
        for (int j = 0; j < 4; ++j) acc[i][j] = 0.0f;
    }

    const int kb_start = (t >= 2) ? (t - 2) : 0;
    const int n_win    = t - kb_start + 1;
    const int nglob    = (t >= 3) ? (t - 2) : 0;
    const int n_tiles  = n_win + (nglob > 0 ? 1 : 0);

    for (int it = 0; it < n_tiles; ++it) {
        const bool is_glob = (it == n_win);
        const int  kcol0   = (kb_start + it) * 64;

        __syncthreads();

        for (int e = tid; e < 1024; e += 256) {
            const int tok = e >> 4;
            const int d4  = (e & 15) * 4;
            int key;
            bool valid;
            if (is_glob) { key = tok * STRIDE; valid = (tok < nglob); }
            else         { key = kcol0 + tok;  valid = true; }
            float4 kv, vv;
            if (valid) {
                const float* kp = qkv + base + (size_t)key * QKV_LD + DMODEL + h * HDIM + d4;
                kv = *(const float4*)kp;
                vv = *(const float4*)(kp + DMODEL);
            } else {
                kv = make_float4(0.f, 0.f, 0.f, 0.f);
                vv = kv;
            }
            Kt[(d4 + 0) * APITCH + tok] = kv.x;
            Kt[(d4 + 1) * APITCH + tok] = kv.y;
            Kt[(d4 + 2) * APITCH + tok] = kv.z;
            Kt[(d4 + 3) * APITCH + tok] = kv.w;
            *(float4*)&Vs[tok * APITCH + d4] = vv;
        }
        __syncthreads();

        float s[4][4];
#pragma unroll
        for (int i = 0; i < 4; ++i)
#pragma unroll
            for (int j = 0; j < 4; ++j) s[i][j] = 0.0f;

#pragma unroll 8
        for (int k = 0; k < 64; ++k) {
            float4 q4 = *(const float4*)&Qt[k * APITCH + ty * 4];
            float4 k4 = *(const float4*)&Kt[k * APITCH + tx * 4];
            float qa[4] = {q4.x, q4.y, q4.z, q4.w};
            float ka[4] = {k4.x, k4.y, k4.z, k4.w};
#pragma unroll
            for (int i = 0; i < 4; ++i)
#pragma unroll
                for (int j = 0; j < 4; ++j)
                    s[i][j] = fmaf(qa[i], ka[j], s[i][j]);
        }

#pragma unroll
        for (int i = 0; i < 4; ++i) {
            const int row = r0 + ty * 4 + i;
#pragma unroll
            for (int j = 0; j < 4; ++j) {
                bool ok;
                if (is_glob) {
                    ok = (tx * 4 + j) < nglob;
                } else {
                    const int col = kcol0 + tx * 4 + j;
                    ok = (col <= row) && ((row - col) <= (WINDOW - 1) || (col & (STRIDE - 1)) == 0);
                }
                s[i][j] = ok ? s[i][j] * 0.125f : -3.0e38f;
            }
        }

#pragma unroll
        for (int i = 0; i < 4; ++i) {
            float mx = fmaxf(fmaxf(s[i][0], s[i][1]), fmaxf(s[i][2], s[i][3]));
#pragma unroll
            for (int off = 8; off >= 1; off >>= 1)
                mx = fmaxf(mx, __shfl_xor_sync(0xffffffffu, mx, off, 16));
            const float mnew = fmaxf(m_i[i], mx);
            const float alpha = __expf(m_i[i] - mnew);
            float rs = 0.0f;
#pragma unroll
            for (int j = 0; j < 4; ++j) {
                const float p = __expf(s[i][j] - mnew);
                Ps[(ty * 4 + i) * APITCH + tx * 4 + j] = p;
                rs += p;
            }
#pragma unroll
            for (int off = 8; off >= 1; off >>= 1)
                rs += __shfl_xor_sync(0xffffffffu, rs, off, 16);
            l_i[i] = l_i[i] * alpha + rs;
            m_i[i] = mnew;
#pragma unroll
            for (int j = 0; j < 4; ++j) acc[i][j] *= alpha;
        }
        __syncthreads();

#pragma unroll 8
        for (int j = 0; j < 64; ++j) {
            float4 v4 = *(const float4*)&Vs[j * APITCH + tx * 4];
            float va[4] = {v4.x, v4.y, v4.z, v4.w};
            float pa[4];
#pragma unroll
            for (int i = 0; i < 4; ++i) pa[i] = Ps[(ty * 4 + i) * APITCH + j];
#pragma unroll
            for (int i = 0; i < 4; ++i)
#pragma unroll
                for (int d = 0; d < 4; ++d)
                    acc[i][d] = fmaf(pa[i], va[d], acc[i][d]);
        }
    }

#pragma unroll
    for (int i = 0; i < 4; ++i) {
        const float inv = 1.0f / l_i[i];
        const size_t row = (size_t)b * SEQ + r0 + ty * 4 + i;
        float4 o = make_float4(acc[i][0] * inv, acc[i][1] * inv,
                               acc[i][2] * inv, acc[i][3] * inv);
        *(float4*)&y[row * DMODEL + h * HDIM + tx * 4] = o;
    }
}

// ---------------------------------------------------------------------------
extern "C" void kernel_launch(void* const* d_in, const int* in_sizes, int n_in,
                              void* d_out, int out_size)
{
    const float* x     = (const float*)d_in[0];
    const float* Wqkv  = (const float*)d_in[1];
    const float* Wproj = (const float*)d_in[2];
    float* out = (float*)d_out;

    float *qkv = nullptr, *y = nullptr;
    cudaGetSymbolAddress((void**)&qkv, g_qkv);
    cudaGetSymbolAddress((void**)&y, g_y);

    cudaFuncSetAttribute(tgemm, cudaFuncAttributeMaxDynamicSharedMemorySize, GEMM_SMEM);
    cudaFuncSetAttribute(sparse_attn, cudaFuncAttributeMaxDynamicSharedMemorySize, ATTN_SMEM);

    // 1) QKV projection: [4096,1024] @ [1024,3072]  (tf32 tensor cores)
    tgemm<<<dim3(QKV_LD / 128, NTOK / 128), 256, GEMM_SMEM>>>(x, Wqkv, qkv, NTOK, QKV_LD, DMODEL);

    // 2) Sparse attention
    sparse_attn<<<dim3(SEQ / 64, NHEADS, BATCH), 256, ATTN_SMEM>>>(qkv, y);

    // 3) Output projection: [4096,1024] @ [1024,1024]  (tf32 tensor cores)
    tgemm<<<dim3(DMODEL / 128, NTOK / 128), 256, GEMM_SMEM>>>(y, Wproj, out, NTOK, DMODEL, DMODEL);
}

// round 5
// speedup vs baseline: 2.4204x; 1.1995x over previous
#include <cuda_runtime.h>
#include <cstdint>
#include <cfloat>

// Problem constants
#define BATCH   2
#define SEQ     2048
#define DMODEL  1024
#define NHEADS  16
#define HDIM    64
#define QKV_LD  3072
#define NTOK    (BATCH * SEQ)      // 4096
#define WINDOW  128
#define STRIDE  64

// Scratch (device globals: no allocation allowed)
__device__ float g_qkv[(size_t)NTOK * QKV_LD];   // 4096 x 3072
__device__ float g_y[(size_t)NTOK * DMODEL];     // 4096 x 1024

// ===========================================================================
// TF32 mma.sync GEMM, v2: C[M,N] = A[M,K] @ B[K,N], row-major.
// CTA tile 256x128, BK=16, 256 threads = 8 warps in 4(M) x 2(N) grid,
// warp tile 64x64 -> 4x8 grid of m16n8k8 tf32 mma.sync.
// Bigger warp tile cuts cross-warp fragment re-reads (L1-bound fix vs R3).
// A fragments via ldmatrix.x4.b16 (tf32 = b16-pair trick) from pitch-20 rows
// (80B stride = 5 mod 8 sixteen-byte units -> conflict-free); B via scalar
// LDS from pitch-136 [k][n] tile (banks 8k+n distinct).
// Dynamic smem 58KB double-buffered; gmem prefetch through registers.
// Requires M%256==0, N%128==0, K%16==0.
// ===========================================================================
#define BM 256
#define BN 128
#define BK 16
#define AP 20    // A row pitch (floats)
#define BP 136   // B row pitch (floats)
#define GEMM_SMEM ((2 * BM * AP + 2 * BK * BP) * (int)sizeof(float))  // 58368 B

__device__ __forceinline__ unsigned f2tf(float f) {
    unsigned u;
    asm("cvt.rna.tf32.f32 %0, %1;" : "=r"(u) : "f"(f));
    return u;
}
__device__ __forceinline__ float4 cvt4(float4 v) {
    float4 t;
    t.x = __uint_as_float(f2tf(v.x));
    t.y = __uint_as_float(f2tf(v.y));
    t.z = __uint_as_float(f2tf(v.z));
    t.w = __uint_as_float(f2tf(v.w));
    return t;
}

__global__ __launch_bounds__(256, 1) void tgemm(
    const float* __restrict__ A, const float* __restrict__ B,
    float* __restrict__ C, int M, int N, int K)
{
    extern __shared__ float sm[];
    float* As0 = sm;                    // [2][BM*AP]  ([m][k])
    float* Bs0 = sm + 2 * BM * AP;      // [2][BK*BP]  ([k][n])

    const int tid  = threadIdx.x;
    const int lane = tid & 31;
    const int wid  = tid >> 5;
    const int warp_m = wid >> 1;         // 0..3
    const int warp_n = wid & 1;          // 0..1
    const int row0 = blockIdx.y * BM;
    const int col0 = blockIdx.x * BN;

    // A loader: 4 passes of (64 rows x 16 k), one float4/thread/pass
    const int ar = tid >> 2;             // 0..63
    const int ak = (tid & 3) * 4;        // 0,4,8,12
    // B loader: 16 rows x 128 cols, two float4/thread
    const int bk = tid >> 4;             // 0..15
    const int bn = (tid & 15) * 8;       // 0..120

    float acc[4][8][4];
#pragma unroll
    for (int mi = 0; mi < 4; ++mi)
#pragma unroll
        for (int ni = 0; ni < 8; ++ni)
#pragma unroll
            for (int e = 0; e < 4; ++e) acc[mi][ni][e] = 0.0f;

    const int nk = K / BK;

    float4 ra[4], rb[2];
    // ---- prologue: load + stage chunk 0 ----
#pragma unroll
    for (int p = 0; p < 4; ++p)
        ra[p] = *(const float4*)(A + (size_t)(row0 + p * 64 + ar) * K + ak);
    rb[0] = *(const float4*)(B + (size_t)bk * N + col0 + bn);
    rb[1] = *(const float4*)(B + (size_t)bk * N + col0 + bn + 4);
#pragma unroll
    for (int p = 0; p < 4; ++p)
        *(float4*)&As0[(p * 64 + ar) * AP + ak] = cvt4(ra[p]);
    *(float4*)&Bs0[bk * BP + bn]     = cvt4(rb[0]);
    *(float4*)&Bs0[bk * BP + bn + 4] = cvt4(rb[1]);
    __syncthreads();

    const int lrow = lane & 15;
    const int lk4  = (lane & 16) ? 4 : 0;
    const int bkr  = lane & 3;
    const int bnc  = warp_n * 64 + (lane >> 2);

    for (int it = 0; it < nk; ++it) {
        const int cur = it & 1;

        // prefetch next chunk (gmem -> regs)
        if (it + 1 < nk) {
            const int k0 = (it + 1) * BK;
#pragma unroll
            for (int p = 0; p < 4; ++p)
                ra[p] = *(const float4*)(A + (size_t)(row0 + p * 64 + ar) * K + k0 + ak);
            rb[0] = *(const float4*)(B + (size_t)(k0 + bk) * N + col0 + bn);
            rb[1] = *(const float4*)(B + (size_t)(k0 + bk) * N + col0 + bn + 4);
        }

        // ---- compute from smem[cur] ----
        const float*   Ac  = As0 + cur * BM * AP;
        const float*   Bc  = Bs0 + cur * BK * BP;
        const unsigned smA = (unsigned)__cvta_generic_to_shared(Ac);
#pragma unroll
        for (int ks = 0; ks < 2; ++ks) {
            unsigned a[4][4];
#pragma unroll
            for (int mi = 0; mi < 4; ++mi) {
                unsigned ad = smA +
                    (((warp_m * 64 + mi * 16 + lrow) * AP + ks * 8 + lk4) << 2);
                asm volatile(
                    "ldmatrix.sync.aligned.m8n8.x4.shared.b16 {%0,%1,%2,%3}, [%4];"
                    : "=r"(a[mi][0]), "=r"(a[mi][1]), "=r"(a[mi][2]), "=r"(a[mi][3])
                    : "r"(ad));
            }
            unsigned b0[8], b1[8];
            const int krow = ks * 8 + bkr;
#pragma unroll
            for (int ni = 0; ni < 8; ++ni) {
                b0[ni] = __float_as_uint(Bc[krow * BP + bnc + ni * 8]);
                b1[ni] = __float_as_uint(Bc[(krow + 4) * BP + bnc + ni * 8]);
            }
#pragma unroll
            for (int mi = 0; mi < 4; ++mi)
#pragma unroll
                for (int ni = 0; ni < 8; ++ni) {
                    asm volatile(
                        "mma.sync.aligned.m16n8k8.row.col.f32.tf32.tf32.f32 "
                        "{%0,%1,%2,%3}, {%4,%5,%6,%7}, {%8,%9}, {%0,%1,%2,%3};"
                        : "+f"(acc[mi][ni][0]), "+f"(acc[mi][ni][1]),
                          "+f"(acc[mi][ni][2]), "+f"(acc[mi][ni][3])
                        : "r"(a[mi][0]), "r"(a[mi][1]), "r"(a[mi][2]), "r"(a[mi][3]),
                          "r"(b0[ni]), "r"(b1[ni]));
                }
        }

        // stage next chunk (regs -> smem[cur^1])
        if (it + 1 < nk) {
            float* An = As0 + (cur ^ 1) * BM * AP;
            float* Bn = Bs0 + (cur ^ 1) * BK * BP;
#pragma unroll
            for (int p = 0; p < 4; ++p)
                *(float4*)&An[(p * 64 + ar) * AP + ak] = cvt4(ra[p]);
            *(float4*)&Bn[bk * BP + bn]     = cvt4(rb[0]);
            *(float4*)&Bn[bk * BP + bn + 4] = cvt4(rb[1]);
        }
        __syncthreads();
    }

    // ---- epilogue ----
    const int g  = lane >> 2;
    const int tg = lane & 3;
#pragma unroll
    for (int mi = 0; mi < 4; ++mi) {
#pragma unroll
        for (int ni = 0; ni < 8; ++ni) {
            const int row = row0 + warp_m * 64 + mi * 16 + g;
            const int col = col0 + warp_n * 64 + ni * 8 + 2 * tg;
            *(float2*)&C[(size_t)row * N + col] =
                make_float2(acc[mi][ni][0], acc[mi][ni][1]);
            *(float2*)&C[(size_t)(row + 8) * N + col] =
                make_float2(acc[mi][ni][2], acc[mi][ni][3]);
        }
    }
}

// ---------------------------------------------------------------------------
// Sparse flash attention (unchanged from R1).
// ---------------------------------------------------------------------------
#define APITCH 68
#define ATTN_SMEM (4 * 64 * APITCH * (int)sizeof(float))

__global__ __launch_bounds__(256) void sparse_attn(
    const float* __restrict__ qkv, float* __restrict__ y)
{
    extern __shared__ float smf[];
    float* Qt = smf;
    float* Kt = Qt + 64 * APITCH;
    float* Vs = Kt + 64 * APITCH;
    float* Ps = Vs + 64 * APITCH;

    const int t   = blockIdx.x;
    const int h   = blockIdx.y;
    const int b   = blockIdx.z;
    const int tid = threadIdx.x;
    const int tx  = tid & 15;
    const int ty  = tid >> 4;
    const int r0  = t * 64;

    const size_t base = (size_t)b * SEQ * QKV_LD;

    for (int e = tid; e < 1024; e += 256) {
        const int tok = e >> 4;
        const int d4  = (e & 15) * 4;
        float4 v = *(const float4*)(qkv + base + (size_t)(r0 + tok) * QKV_LD + h * HDIM + d4);
        Qt[(d4 + 0) * APITCH + tok] = v.x;
        Qt[(d4 + 1) * APITCH + tok] = v.y;
        Qt[(d4 + 2) * APITCH + tok] = v.z;
        Qt[(d4 + 3) * APITCH + tok] = v.w;
    }

    float m_i[4], l_i[4], acc[4][4];
#pragma unroll
    for (int i = 0; i < 4; ++i) {
        m_i[i] = -3.0e38f;
        l_i[i] = 0.0f;
#pragma unroll
        for (int j = 0; j < 4; ++j) acc[i][j] = 0.0f;
    }

    const int kb_start = (t >= 2) ? (t - 2) : 0;
    const int n_win    = t - kb_start + 1;
    const int nglob    = (t >= 3) ? (t - 2) : 0;
    const int n_tiles  = n_win + (nglob > 0 ? 1 : 0);

    for (int it = 0; it < n_tiles; ++it) {
        const bool is_glob = (it == n_win);
        const int  kcol0   = (kb_start + it) * 64;

        __syncthreads();

        for (int e = tid; e < 1024; e += 256) {
            const int tok = e >> 4;
            const int d4  = (e & 15) * 4;
            int key;
            bool valid;
            if (is_glob) { key = tok * STRIDE; valid = (tok < nglob); }
            else         { key = kcol0 + tok;  valid = true; }
            float4 kv, vv;
            if (valid) {
                const float* kp = qkv + base + (size_t)key * QKV_LD + DMODEL + h * HDIM + d4;
                kv = *(const float4*)kp;
                vv = *(const float4*)(kp + DMODEL);
            } else {
                kv = make_float4(0.f, 0.f, 0.f, 0.f);
                vv = kv;
            }
            Kt[(d4 + 0) * APITCH + tok] = kv.x;
            Kt[(d4 + 1) * APITCH + tok] = kv.y;
            Kt[(d4 + 2) * APITCH + tok] = kv.z;
            Kt[(d4 + 3) * APITCH + tok] = kv.w;
            *(float4*)&Vs[tok * APITCH + d4] = vv;
        }
        __syncthreads();

        float s[4][4];
#pragma unroll
        for (int i = 0; i < 4; ++i)
#pragma unroll
            for (int j = 0; j < 4; ++j) s[i][j] = 0.0f;

#pragma unroll 8
        for (int k = 0; k < 64; ++k) {
            float4 q4 = *(const float4*)&Qt[k * APITCH + ty * 4];
            float4 k4 = *(const float4*)&Kt[k * APITCH + tx * 4];
            float qa[4] = {q4.x, q4.y, q4.z, q4.w};
            float ka[4] = {k4.x, k4.y, k4.z, k4.w};
#pragma unroll
            for (int i = 0; i < 4; ++i)
#pragma unroll
                for (int j = 0; j < 4; ++j)
                    s[i][j] = fmaf(qa[i], ka[j], s[i][j]);
        }

#pragma unroll
        for (int i = 0; i < 4; ++i) {
            const int row = r0 + ty * 4 + i;
#pragma unroll
            for (int j = 0; j < 4; ++j) {
                bool ok;
                if (is_glob) {
                    ok = (tx * 4 + j) < nglob;
                } else {
                    const int col = kcol0 + tx * 4 + j;
                    ok = (col <= row) && ((row - col) <= (WINDOW - 1) || (col & (STRIDE - 1)) == 0);
                }
                s[i][j] = ok ? s[i][j] * 0.125f : -3.0e38f;
            }
        }

#pragma unroll
        for (int i = 0; i < 4; ++i) {
            float mx = fmaxf(fmaxf(s[i][0], s[i][1]), fmaxf(s[i][2], s[i][3]));
#pragma unroll
            for (int off = 8; off >= 1; off >>= 1)
                mx = fmaxf(mx, __shfl_xor_sync(0xffffffffu, mx, off, 16));
            const float mnew = fmaxf(m_i[i], mx);
            const float alpha = __expf(m_i[i] - mnew);
            float rs = 0.0f;
#pragma unroll
            for (int j = 0; j < 4; ++j) {
                const float p = __expf(s[i][j] - mnew);
                Ps[(ty * 4 + i) * APITCH + tx * 4 + j] = p;
                rs += p;
            }
#pragma unroll
            for (int off = 8; off >= 1; off >>= 1)
                rs += __shfl_xor_sync(0xffffffffu, rs, off, 16);
            l_i[i] = l_i[i] * alpha + rs;
            m_i[i] = mnew;
#pragma unroll
            for (int j = 0; j < 4; ++j) acc[i][j] *= alpha;
        }
        __syncthreads();

#pragma unroll 8
        for (int j = 0; j < 64; ++j) {
            float4 v4 = *(const float4*)&Vs[j * APITCH + tx * 4];
            float va[4] = {v4.x, v4.y, v4.z, v4.w};
            float pa[4];
#pragma unroll
            for (int i = 0; i < 4; ++i) pa[i] = Ps[(ty * 4 + i) * APITCH + j];
#pragma unroll
            for (int i = 0; i < 4; ++i)
#pragma unroll
                for (int d = 0; d < 4; ++d)
                    acc[i][d] = fmaf(pa[i], va[d], acc[i][d]);
        }
    }

#pragma unroll
    for (int i = 0; i < 4; ++i) {
        const float inv = 1.0f / l_i[i];
        const size_t row = (size_t)b * SEQ + r0 + ty * 4 + i;
        float4 o = make_float4(acc[i][0] * inv, acc[i][1] * inv,
                               acc[i][2] * inv, acc[i][3] * inv);
        *(float4*)&y[row * DMODEL + h * HDIM + tx * 4] = o;
    }
}

// ---------------------------------------------------------------------------
extern "C" void kernel_launch(void* const* d_in, const int* in_sizes, int n_in,
                              void* d_out, int out_size)
{
    const float* x     = (const float*)d_in[0];
    const float* Wqkv  = (const float*)d_in[1];
    const float* Wproj = (const float*)d_in[2];
    float* out = (float*)d_out;

    float *qkv = nullptr, *y = nullptr;
    cudaGetSymbolAddress((void**)&qkv, g_qkv);
    cudaGetSymbolAddress((void**)&y, g_y);

    cudaFuncSetAttribute(tgemm, cudaFuncAttributeMaxDynamicSharedMemorySize, GEMM_SMEM);
    cudaFuncSetAttribute(sparse_attn, cudaFuncAttributeMaxDynamicSharedMemorySize, ATTN_SMEM);

    // 1) QKV projection: [4096,1024] @ [1024,3072]  (tf32 mma.sync)
    tgemm<<<dim3(QKV_LD / BN, NTOK / BM), 256, GEMM_SMEM>>>(x, Wqkv, qkv, NTOK, QKV_LD, DMODEL);

    // 2) Sparse attention
    sparse_attn<<<dim3(SEQ / 64, NHEADS, BATCH), 256, ATTN_SMEM>>>(qkv, y);

    // 3) Output projection: [4096,1024] @ [1024,1024]  (tf32 mma.sync)
    tgemm<<<dim3(DMODEL / BN, NTOK / BM), 256, GEMM_SMEM>>>(y, Wproj, out, NTOK, DMODEL, DMODEL);
}